// round 17
// baseline (speedup 1.0000x reference)
#include <cuda_runtime.h>

// ContextEmbedding: per-token embedding assembly.
//   out[t, :] = special_emb(tok) + cls_branch(tok) + ctx_branch(tok)
// HBM-store-bound workload (134MB out), but R15 ncu showed it scheduling-
// limited (issue 12.8%, DRAM 32%, 16384 tiny CTAs). This version: 4 tokens
// per warp via one int4 token-id load -> 4096 CTAs, 4x store work per
// exposed load latency.

#define D_MODEL 256
#define SPECIAL_OFFSET 68
#define NUM_SPECIAL 8
#define NUM_CONTEXT 16
#define LN_EPS 1e-5f

__device__ __forceinline__ void store_cs(float4* p, float4 v) {
    asm volatile("st.global.cs.v4.f32 [%0], {%1,%2,%3,%4};"
                 :: "l"(p), "f"(v.x), "f"(v.y), "f"(v.z), "f"(v.w) : "memory");
}

// Handle one special token (sid in [0,8)). Warp-collective.
__device__ __forceinline__ void handle_special(
    int sid, int tok_idx, int lane,
    const float* __restrict__ feat,
    const float* __restrict__ special_table,
    const float* __restrict__ cls_w,  const float* __restrict__ cls_b,
    const float* __restrict__ cls_g,  const float* __restrict__ cls_beta,
    const float* __restrict__ ctx_w,  const float* __restrict__ ctx_b,
    const float* __restrict__ ctx_g,  const float* __restrict__ ctx_beta,
    float4* o)
{
    const float4* st = reinterpret_cast<const float4*>(special_table + sid * D_MODEL);
    float4 e0 = __ldg(st + lane);
    float4 e1 = __ldg(st + lane + 32);

    if (sid > 1) {                   // special but not CLS/CONTEXT
        store_cs(o + lane,      e0);
        store_cs(o + lane + 32, e1);
        return;
    }

    const bool  is_cls = (sid == 0);
    const int   K      = is_cls ? 3 : NUM_CONTEXT;
    const float* w     = is_cls ? cls_w    : ctx_w;
    const float* bvec  = is_cls ? cls_b    : ctx_b;
    const float* gvec  = is_cls ? cls_g    : ctx_g;
    const float* bevec = is_cls ? cls_beta : ctx_beta;
    const float* f     = feat + (size_t)tok_idx * NUM_CONTEXT;

    float4 y0 = __ldg(reinterpret_cast<const float4*>(bvec) + lane);
    float4 y1 = __ldg(reinterpret_cast<const float4*>(bvec) + lane + 32);
    #pragma unroll 4
    for (int k = 0; k < K; ++k) {
        const float fk = __ldg(f + k);   // broadcast
        const float4 w0 = __ldg(reinterpret_cast<const float4*>(w + k * D_MODEL) + lane);
        const float4 w1 = __ldg(reinterpret_cast<const float4*>(w + k * D_MODEL) + lane + 32);
        y0.x = fmaf(fk, w0.x, y0.x); y0.y = fmaf(fk, w0.y, y0.y);
        y0.z = fmaf(fk, w0.z, y0.z); y0.w = fmaf(fk, w0.w, y0.w);
        y1.x = fmaf(fk, w1.x, y1.x); y1.y = fmaf(fk, w1.y, y1.y);
        y1.z = fmaf(fk, w1.z, y1.z); y1.w = fmaf(fk, w1.w, y1.w);
    }

    float s  = y0.x + y0.y + y0.z + y0.w + y1.x + y1.y + y1.z + y1.w;
    float ss = y0.x*y0.x + y0.y*y0.y + y0.z*y0.z + y0.w*y0.w
             + y1.x*y1.x + y1.y*y1.y + y1.z*y1.z + y1.w*y1.w;
    #pragma unroll
    for (int off = 16; off > 0; off >>= 1) {
        s  += __shfl_xor_sync(0xffffffffu, s,  off);
        ss += __shfl_xor_sync(0xffffffffu, ss, off);
    }
    const float mean = s * (1.0f / D_MODEL);
    const float var  = fmaxf(ss * (1.0f / D_MODEL) - mean * mean, 0.0f);
    const float rstd = rsqrtf(var + LN_EPS);

    const float4 g0  = __ldg(reinterpret_cast<const float4*>(gvec) + lane);
    const float4 g1  = __ldg(reinterpret_cast<const float4*>(gvec) + lane + 32);
    const float4 be0 = __ldg(reinterpret_cast<const float4*>(bevec) + lane);
    const float4 be1 = __ldg(reinterpret_cast<const float4*>(bevec) + lane + 32);

    float4 r0, r1;
    r0.x = e0.x + fmaxf((y0.x - mean) * rstd * g0.x + be0.x, 0.0f);
    r0.y = e0.y + fmaxf((y0.y - mean) * rstd * g0.y + be0.y, 0.0f);
    r0.z = e0.z + fmaxf((y0.z - mean) * rstd * g0.z + be0.z, 0.0f);
    r0.w = e0.w + fmaxf((y0.w - mean) * rstd * g0.w + be0.w, 0.0f);
    r1.x = e1.x + fmaxf((y1.x - mean) * rstd * g1.x + be1.x, 0.0f);
    r1.y = e1.y + fmaxf((y1.y - mean) * rstd * g1.y + be1.y, 0.0f);
    r1.z = e1.z + fmaxf((y1.z - mean) * rstd * g1.z + be1.z, 0.0f);
    r1.w = e1.w + fmaxf((y1.w - mean) * rstd * g1.w + be1.w, 0.0f);

    store_cs(o + lane,      r0);
    store_cs(o + lane + 32, r1);
}

#define TOKENS_PER_WARP 4

__global__ __launch_bounds__(256) void context_embedding_kernel(
    const int*   __restrict__ token_ids,
    const float* __restrict__ feat,          // [T, 16]
    const float* __restrict__ special_table, // [8, 256]
    const float* __restrict__ cls_w,  const float* __restrict__ cls_b,
    const float* __restrict__ cls_g,  const float* __restrict__ cls_beta,
    const float* __restrict__ ctx_w,  const float* __restrict__ ctx_b,
    const float* __restrict__ ctx_g,  const float* __restrict__ ctx_beta,
    float* __restrict__ out,                 // [T, 256]
    int n_tokens)
{
    const int warp = (blockIdx.x * blockDim.x + threadIdx.x) >> 5;
    const int lane = threadIdx.x & 31;
    const int base = warp * TOKENS_PER_WARP;
    if (base >= n_tokens) return;

    const float4 z = make_float4(0.f, 0.f, 0.f, 0.f);

    if (base + TOKENS_PER_WARP <= n_tokens) {
        // One 16B broadcast load covers 4 tokens.
        const int4 t4 = __ldg(reinterpret_cast<const int4*>(token_ids) + warp);
        const int sid0 = t4.x - SPECIAL_OFFSET;
        const int sid1 = t4.y - SPECIAL_OFFSET;
        const int sid2 = t4.z - SPECIAL_OFFSET;
        const int sid3 = t4.w - SPECIAL_OFFSET;
        const bool sp0 = (unsigned)sid0 < NUM_SPECIAL;
        const bool sp1 = (unsigned)sid1 < NUM_SPECIAL;
        const bool sp2 = (unsigned)sid2 < NUM_SPECIAL;
        const bool sp3 = (unsigned)sid3 < NUM_SPECIAL;

        float4* o = reinterpret_cast<float4*>(out + (size_t)base * D_MODEL);

        if (!(sp0 | sp1 | sp2 | sp3)) {
            // Common case (~64% of warps): 8 independent streaming stores.
            store_cs(o + lane,       z); store_cs(o + lane +  32, z);
            store_cs(o + lane +  64, z); store_cs(o + lane +  96, z);
            store_cs(o + lane + 128, z); store_cs(o + lane + 160, z);
            store_cs(o + lane + 192, z); store_cs(o + lane + 224, z);
            return;
        }

        const int  sids[TOKENS_PER_WARP] = {sid0, sid1, sid2, sid3};
        const bool sps [TOKENS_PER_WARP] = {sp0, sp1, sp2, sp3};
        #pragma unroll 1
        for (int j = 0; j < TOKENS_PER_WARP; ++j) {
            float4* oj = o + j * (D_MODEL / 4);
            if (!sps[j]) {
                store_cs(oj + lane,      z);
                store_cs(oj + lane + 32, z);
            } else {
                handle_special(sids[j], base + j, lane, feat, special_table,
                               cls_w, cls_b, cls_g, cls_beta,
                               ctx_w, ctx_b, ctx_g, ctx_beta, oj);
            }
        }
    } else {
        // Tail: per-token scalar loads with bounds guard.
        #pragma unroll 1
        for (int j = 0; j < TOKENS_PER_WARP; ++j) {
            const int t = base + j;
            if (t >= n_tokens) break;
            const int sid = __ldg(token_ids + t) - SPECIAL_OFFSET;
            float4* oj = reinterpret_cast<float4*>(out + (size_t)t * D_MODEL);
            if ((unsigned)sid >= NUM_SPECIAL) {
                store_cs(oj + lane,      z);
                store_cs(oj + lane + 32, z);
            } else {
                handle_special(sid, t, lane, feat, special_table,
                               cls_w, cls_b, cls_g, cls_beta,
                               ctx_w, ctx_b, ctx_g, ctx_beta, oj);
            }
        }
    }
}

extern "C" void kernel_launch(void* const* d_in, const int* in_sizes, int n_in,
                              void* d_out, int out_size) {
    const int*   token_ids = (const int*)  d_in[0];
    const float* feat      = (const float*)d_in[1];
    const float* sp_table  = (const float*)d_in[2];
    const float* cls_w     = (const float*)d_in[3];
    const float* cls_b     = (const float*)d_in[4];
    const float* cls_g     = (const float*)d_in[5];
    const float* cls_beta  = (const float*)d_in[6];
    const float* ctx_w     = (const float*)d_in[7];
    const float* ctx_b     = (const float*)d_in[8];
    const float* ctx_g     = (const float*)d_in[9];
    const float* ctx_beta  = (const float*)d_in[10];
    float* out = (float*)d_out;

    int n_tokens = in_sizes[0];                 // B*S = 131072
    const int max_tokens = out_size / D_MODEL;
    if (n_tokens > max_tokens) n_tokens = max_tokens;

    const int WARPS_PER_BLOCK = 8;              // 256 threads
    const int warps_needed = (n_tokens + TOKENS_PER_WARP - 1) / TOKENS_PER_WARP;
    const int blocks = (warps_needed + WARPS_PER_BLOCK - 1) / WARPS_PER_BLOCK;

    context_embedding_kernel<<<blocks, 256>>>(
        token_ids, feat, sp_table,
        cls_w, cls_b, cls_g, cls_beta,
        ctx_w, ctx_b, ctx_g, ctx_beta,
        out, n_tokens);
}